// round 3
// baseline (speedup 1.0000x reference)
#include <cuda_runtime.h>
#include <cuda_fp16.h>
#include <cstdint>

// Problem dims
#define N_SAMPLES 2048
#define D_FEAT    64
#define P_PAIRS   2016
#define INNER     32
#define KDIM      64512   // P_PAIRS * INNER
#define HIDDEN    2048
#define CLASSES   10

// -------------------- scratch (device globals; no allocation) --------------------
__device__ __half g_u [(size_t)N_SAMPLES * KDIM];   // 264 MB: relu(pairs@Wu+bu), fp16, row-major [N, K]
__device__ __half g_bt[(size_t)HIDDEN    * KDIM];   // 264 MB: Wv^T fp16, K-major [HIDDEN, K]
__device__ float  g_v [(size_t)N_SAMPLES * HIDDEN]; // 16 MB: relu(u@Wv+bv)
__device__ float  g_xT[(size_t)D_FEAT * N_SAMPLES]; // x transposed

// -------------------- helpers --------------------
__device__ __forceinline__ uint32_t smem_u32(const void* p) {
    return (uint32_t)__cvta_generic_to_shared(p);
}
__device__ __forceinline__ void cp_async16(uint32_t dst, const void* src) {
    asm volatile("cp.async.cg.shared.global [%0], [%1], 16;" :: "r"(dst), "l"(src) : "memory");
}
__device__ __forceinline__ void cp_commit() {
    asm volatile("cp.async.commit_group;" ::: "memory");
}
template <int N>
__device__ __forceinline__ void cp_wait() {
    asm volatile("cp.async.wait_group %0;" :: "n"(N) : "memory");
}
__device__ __forceinline__ void ldsm_x4(uint32_t* r, uint32_t addr) {
    asm volatile("ldmatrix.sync.aligned.m8n8.x4.shared.b16 {%0,%1,%2,%3}, [%4];"
                 : "=r"(r[0]), "=r"(r[1]), "=r"(r[2]), "=r"(r[3]) : "r"(addr));
}
__device__ __forceinline__ void mma16816(float* c, const uint32_t* a, const uint32_t* b) {
    asm volatile(
        "mma.sync.aligned.m16n8k16.row.col.f32.f16.f16.f32 "
        "{%0,%1,%2,%3}, {%4,%5,%6,%7}, {%8,%9}, {%0,%1,%2,%3};"
        : "+f"(c[0]), "+f"(c[1]), "+f"(c[2]), "+f"(c[3])
        : "r"(a[0]), "r"(a[1]), "r"(a[2]), "r"(a[3]), "r"(b[0]), "r"(b[1]));
}

// ==================== kernel 1: transpose x ====================
__global__ void k_transpose_x(const float* __restrict__ x) {
    int idx = blockIdx.x * blockDim.x + threadIdx.x;
    if (idx < N_SAMPLES * D_FEAT) {
        int n = idx >> 6, d = idx & 63;
        g_xT[(size_t)d * N_SAMPLES + n] = x[idx];
    }
}

// ==================== kernel 2: pairwise Linear(2,32)+ReLU -> u (fp16) ====================
__global__ void k_pairs(const float* __restrict__ Wu, const float* __restrict__ bu) {
    int p = blockIdx.x;
    int a = 0, rem = p;
    while (rem >= (D_FEAT - 1 - a)) { rem -= (D_FEAT - 1 - a); a++; }
    int b = a + 1 + rem;

    __shared__ float w0[INNER], w1[INNER], bb[INNER];
    int tid = threadIdx.x;
    if (tid < INNER) {
        w0[tid] = Wu[(size_t)p * 2 * INNER + tid];
        w1[tid] = Wu[(size_t)p * 2 * INNER + INNER + tid];
        bb[tid] = bu[(size_t)p * INNER + tid];
    }
    __syncthreads();

    const float* xa = g_xT + (size_t)a * N_SAMPLES;
    const float* xb = g_xT + (size_t)b * N_SAMPLES;
    for (int n = tid; n < N_SAMPLES; n += blockDim.x) {
        float va = xa[n], vb = xb[n];
        __half2 outv[INNER / 2];
        #pragma unroll
        for (int i = 0; i < INNER; i += 2) {
            float r0 = fmaf(va, w0[i],     fmaf(vb, w1[i],     bb[i]));
            float r1 = fmaf(va, w0[i + 1], fmaf(vb, w1[i + 1], bb[i + 1]));
            outv[i / 2] = __floats2half2_rn(fmaxf(r0, 0.f), fmaxf(r1, 0.f));
        }
        uint4* dst = reinterpret_cast<uint4*>(g_u + (size_t)n * KDIM + (size_t)p * INNER);
        const uint4* src = reinterpret_cast<const uint4*>(outv);
        dst[0] = src[0]; dst[1] = src[1]; dst[2] = src[2]; dst[3] = src[3];
    }
}

// ==================== kernel 3: Wv [K, HIDDEN] fp32 -> Bt [HIDDEN, K] fp16 ====================
__global__ void k_conv_wv(const float* __restrict__ Wv) {
    __shared__ float tile[32][33];
    int nt0 = blockIdx.x * 32;   // HIDDEN
    int kt0 = blockIdx.y * 32;   // KDIM
    int tx = threadIdx.x, ty = threadIdx.y;  // 32 x 8
    #pragma unroll
    for (int r = 0; r < 4; r++) {
        int k = kt0 + ty + r * 8;
        tile[ty + r * 8][tx] = Wv[(size_t)k * HIDDEN + nt0 + tx];
    }
    __syncthreads();
    #pragma unroll
    for (int r = 0; r < 4; r++) {
        int n = nt0 + ty + r * 8;
        g_bt[(size_t)n * KDIM + kt0 + tx] = __float2half(tile[tx][ty + r * 8]);
    }
}

// ==================== kernel 4: big GEMM v = relu(u @ Wv + bv) via mma.sync ====================
#define BM 128
#define BN 256
#define BK 32
#define STG 4
#define CHUNKS (KDIM / BK)                 // 2016
#define A_STAGE (BM * BK * 2)              // 8192 B
#define B_STAGE (BN * BK * 2)              // 16384 B
#define STAGE_B (A_STAGE + B_STAGE)        // 24576 B
#define SMEM_GEMM (STG * STAGE_B)          // 98304 B

// smem offset for logical (row, kc-16B-chunk): swizzled so ldmatrix (8 consecutive
// rows, fixed kc) is bank-conflict-free.
__device__ __forceinline__ uint32_t sw_off(int row, int kc) {
    return (uint32_t)(row * 64 + ((kc ^ ((row >> 1) & 3)) << 4));
}

__device__ __forceinline__ void load_stage(uint32_t sA, uint32_t sB,
                                           const __half* __restrict__ gA,
                                           const __half* __restrict__ gB,
                                           int kOffHalf, int tid) {
    {   // A: 128 rows x 64 B = 512 chunks, 1 per thread
        int row = tid >> 2, kc = tid & 3;
        const char* src = (const char*)(gA + (size_t)row * KDIM + kOffHalf) + kc * 16;
        cp_async16(sA + sw_off(row, kc), src);
    }
    #pragma unroll
    for (int j = 0; j < 2; j++) {  // B: 256 rows x 64 B = 1024 chunks, 2 per thread
        int idx = tid + j * 512;
        int row = idx >> 2, kc = idx & 3;
        const char* src = (const char*)(gB + (size_t)row * KDIM + kOffHalf) + kc * 16;
        cp_async16(sB + sw_off(row, kc), src);
    }
}

__global__ void __launch_bounds__(512, 1) k_gemm(const float* __restrict__ bv) {
    extern __shared__ char smem[];
    uint32_t sbase = smem_u32(smem);
    int tid = threadIdx.x;
    int lane = tid & 31;
    int wid = tid >> 5;
    int wm = wid >> 3;           // 0..1  (64 rows each)
    int wn = wid & 7;            // 0..7  (32 cols each)
    int bn0 = blockIdx.x * BN;   // 8 n-blocks
    int bm0 = blockIdx.y * BM;   // 16 m-blocks

    const __half* gA = g_u  + (size_t)bm0 * KDIM;
    const __half* gB = g_bt + (size_t)bn0 * KDIM;

    // per-lane ldmatrix row bases
    int g = lane >> 3, sub = lane & 7;
    int rowA_base = wm * 64 + ((g & 1) << 3) + sub;  // + mt*16
    int kcA_base  = g >> 1;                          // + ks*2
    int rowB_base = wn * 32 + ((g >> 1) << 3) + sub; // + q*16
    int kcB_base  = g & 1;                           // + ks*2

    float acc[4][4][4];
    #pragma unroll
    for (int i = 0; i < 4; i++)
        #pragma unroll
        for (int j = 0; j < 4; j++)
            #pragma unroll
            for (int t = 0; t < 4; t++) acc[i][j][t] = 0.f;

    // prologue: fill 3 stages
    #pragma unroll
    for (int s = 0; s < STG - 1; s++) {
        load_stage(sbase + s * STAGE_B, sbase + s * STAGE_B + A_STAGE, gA, gB, s * BK, tid);
        cp_commit();
    }

    int slot = 0;
    for (int k = 0; k < CHUNKS; k++) {
        cp_wait<STG - 2>();      // stage k complete (own thread)
        __syncthreads();         // visible to all; all done reading slot being refilled

        int kpre = k + STG - 1;
        if (kpre < CHUNKS) {
            int ps = (slot + STG - 1) & 3;
            load_stage(sbase + ps * STAGE_B, sbase + ps * STAGE_B + A_STAGE,
                       gA, gB, kpre * BK, tid);
        }
        cp_commit();

        uint32_t aS = sbase + slot * STAGE_B;
        uint32_t bS = aS + A_STAGE;
        #pragma unroll
        for (int ks = 0; ks < 2; ks++) {
            uint32_t afr[4][4], bfr[2][4];
            #pragma unroll
            for (int mt = 0; mt < 4; mt++) {
                int row = rowA_base + mt * 16;
                ldsm_x4(afr[mt], aS + sw_off(row, ks * 2 + kcA_base));
            }
            #pragma unroll
            for (int q = 0; q < 2; q++) {
                int row = rowB_base + q * 16;
                ldsm_x4(bfr[q], bS + sw_off(row, ks * 2 + kcB_base));
            }
            #pragma unroll
            for (int mt = 0; mt < 4; mt++)
                #pragma unroll
                for (int nt = 0; nt < 4; nt++)
                    mma16816(acc[mt][nt], afr[mt], &bfr[nt >> 1][(nt & 1) * 2]);
        }
        slot = (slot + 1) & 3;
    }

    // epilogue: bias + relu, write fp32 v
    int rlo = lane >> 2;         // 0..7
    int cpair = (lane & 3) * 2;  // 0,2,4,6
    #pragma unroll
    for (int mt = 0; mt < 4; mt++) {
        #pragma unroll
        for (int nt = 0; nt < 4; nt++) {
            int col = bn0 + wn * 32 + nt * 8 + cpair;
            float b0 = __ldg(bv + col), b1 = __ldg(bv + col + 1);
            int row0 = bm0 + wm * 64 + mt * 16 + rlo;
            float2 o0, o1;
            o0.x = fmaxf(acc[mt][nt][0] + b0, 0.f);
            o0.y = fmaxf(acc[mt][nt][1] + b1, 0.f);
            o1.x = fmaxf(acc[mt][nt][2] + b0, 0.f);
            o1.y = fmaxf(acc[mt][nt][3] + b1, 0.f);
            *reinterpret_cast<float2*>(g_v + (size_t)row0 * HIDDEN + col) = o0;
            *reinterpret_cast<float2*>(g_v + (size_t)(row0 + 8) * HIDDEN + col) = o1;
        }
    }
}

// ==================== kernel 5: head  out = v @ Wo + bo ====================
__global__ void k_final(const float* __restrict__ Wo, const float* __restrict__ bo,
                        float* __restrict__ out) {
    int n = blockIdx.x, tid = threadIdx.x;
    float acc[CLASSES] = {};
    const float* vrow = g_v + (size_t)n * HIDDEN;
    for (int h = tid; h < HIDDEN; h += 256) {
        float vv = vrow[h];
        const float* wrow = Wo + (size_t)h * CLASSES;
        #pragma unroll
        for (int c = 0; c < CLASSES; c++) acc[c] = fmaf(vv, wrow[c], acc[c]);
    }
    #pragma unroll
    for (int c = 0; c < CLASSES; c++)
        #pragma unroll
        for (int o = 16; o > 0; o >>= 1)
            acc[c] += __shfl_xor_sync(0xffffffffu, acc[c], o);
    __shared__ float part[8][CLASSES];
    if ((tid & 31) == 0) {
        #pragma unroll
        for (int c = 0; c < CLASSES; c++) part[tid >> 5][c] = acc[c];
    }
    __syncthreads();
    if (tid < CLASSES) {
        float s = 0.f;
        #pragma unroll
        for (int w = 0; w < 8; w++) s += part[w][tid];
        out[(size_t)n * CLASSES + tid] = s + bo[tid];
    }
}

// ==================== launch ====================
extern "C" void kernel_launch(void* const* d_in, const int* in_sizes, int n_in,
                              void* d_out, int out_size) {
    const float* x  = (const float*)d_in[0];
    const float* Wu = (const float*)d_in[1];
    const float* bu = (const float*)d_in[2];
    const float* Wv = (const float*)d_in[3];
    const float* bv = (const float*)d_in[4];
    const float* Wo = (const float*)d_in[5];
    const float* bo = (const float*)d_in[6];
    float* out = (float*)d_out;

    cudaFuncSetAttribute(k_gemm, cudaFuncAttributeMaxDynamicSharedMemorySize, SMEM_GEMM);

    k_transpose_x<<<(N_SAMPLES * D_FEAT + 255) / 256, 256>>>(x);
    k_pairs<<<P_PAIRS, 256>>>(Wu, bu);
    k_conv_wv<<<dim3(HIDDEN / 32, KDIM / 32), dim3(32, 8)>>>(Wv);
    k_gemm<<<dim3(HIDDEN / BN, N_SAMPLES / BM), 512, SMEM_GEMM>>>(bv);
    k_final<<<N_SAMPLES, 256>>>(Wo, bo, out);
}